// round 1
// baseline (speedup 1.0000x reference)
#include <cuda_runtime.h>

// Problem constants (fixed by setup_inputs)
#define BATCH   16
#define CHAN    4
#define H_IN    128
#define W_IN    240
#define MAXD    24
#define H_OUT   1024
#define W_OUT   1920

// Scratch for the low-res disparity prediction (pred * 8), 16*128*240 floats = ~2 MB.
__device__ float g_pred[BATCH * H_IN * W_IN];

// ---------------------------------------------------------------------------
// Kernel 1: cost volume + softmax expectation per row.
// One block per (b, y) row. Stage left/right rows (4 channels x 240) in smem.
// ---------------------------------------------------------------------------
__global__ __launch_bounds__(256) void disp_kernel(
    const float* __restrict__ fl, const float* __restrict__ fr)
{
    const int row = blockIdx.x;          // b*H_IN + y
    const int b = row / H_IN;
    const int y = row % H_IN;

    __shared__ float sl[CHAN][W_IN];
    __shared__ float sr[CHAN][W_IN];

    const size_t base = ((size_t)b * CHAN) * H_IN * W_IN + (size_t)y * W_IN;
    for (int i = threadIdx.x; i < CHAN * W_IN; i += blockDim.x) {
        const int c = i / W_IN;
        const int x = i % W_IN;
        const size_t off = base + (size_t)c * (H_IN * W_IN) + x;
        sl[c][x] = fl[off];
        sr[c][x] = fr[off];
    }
    __syncthreads();

    const int x = threadIdx.x;
    if (x < W_IN) {
        const float l0 = sl[0][x], l1 = sl[1][x], l2 = sl[2][x], l3 = sl[3][x];

        float cost[MAXD];
        float cmin = 3.402823e38f;
#pragma unroll
        for (int d = 0; d < MAXD; d++) {
            const int xs = x - d;
            float r0, r1, r2, r3;
            if (xs >= 0) {
                r0 = sr[0][xs]; r1 = sr[1][xs]; r2 = sr[2][xs]; r3 = sr[3][xs];
            } else {
                r0 = r1 = r2 = r3 = 0.0f;   // zero padding
            }
            const float c = fabsf(l0 - r0) + fabsf(l1 - r1)
                          + fabsf(l2 - r2) + fabsf(l3 - r3);
            cost[d] = c;
            cmin = fminf(cmin, c);
        }

        float num = 0.0f, den = 0.0f;
#pragma unroll
        for (int d = 0; d < MAXD; d++) {
            const float e = __expf(cmin - cost[d]);   // softmax(-cost)
            den += e;
            num += (float)d * e;
        }
        // pred * (img_h / h) = pred * 8
        g_pred[row * W_IN + x] = (num / den) * 8.0f;
    }
}

// ---------------------------------------------------------------------------
// Kernel 2: bilinear resize (align_corners) 128x240 -> 1024x1920.
// One thread per float4 of output (coalesced 16B stores). Gathers hit L2.
// ---------------------------------------------------------------------------
__global__ __launch_bounds__(256) void resize_kernel(float* __restrict__ out)
{
    const int W4 = W_OUT / 4;                       // 480
    const int tid = blockIdx.x * blockDim.x + threadIdx.x;
    const int total = BATCH * H_OUT * W4;
    if (tid >= total) return;

    const int ox4 = tid % W4;
    const int t   = tid / W4;
    const int oy  = t % H_OUT;
    const int b   = t / H_OUT;

    const float ysc = (float)(H_IN - 1) / (float)(H_OUT - 1);
    const float xsc = (float)(W_IN - 1) / (float)(W_OUT - 1);

    const float yf = (float)oy * ysc;
    int y0 = (int)floorf(yf);
    if (y0 > H_IN - 1) y0 = H_IN - 1;
    const int y1 = min(y0 + 1, H_IN - 1);
    const float wy = yf - (float)y0;

    const float* __restrict__ row0 = g_pred + (b * H_IN + y0) * W_IN;
    const float* __restrict__ row1 = g_pred + (b * H_IN + y1) * W_IN;

    float4 res;
    float* rp = (float*)&res;
#pragma unroll
    for (int k = 0; k < 4; k++) {
        const int ox = ox4 * 4 + k;
        const float xf = (float)ox * xsc;
        int x0 = (int)floorf(xf);
        if (x0 > W_IN - 1) x0 = W_IN - 1;
        const int x1 = min(x0 + 1, W_IN - 1);
        const float wx = xf - (float)x0;

        const float a = row0[x0] * (1.0f - wy) + row1[x0] * wy;
        const float c = row0[x1] * (1.0f - wy) + row1[x1] * wy;
        rp[k] = a * (1.0f - wx) + c * wx;
    }

    ((float4*)out)[tid] = res;
}

extern "C" void kernel_launch(void* const* d_in, const int* in_sizes, int n_in,
                              void* d_out, int out_size)
{
    const float* feat_l = (const float*)d_in[0];
    const float* feat_r = (const float*)d_in[1];
    float* out = (float*)d_out;

    // Kernel 1: one block per (b, y) row
    disp_kernel<<<BATCH * H_IN, 256>>>(feat_l, feat_r);

    // Kernel 2: one thread per output float4
    const int W4 = W_OUT / 4;
    const int total = BATCH * H_OUT * W4;
    resize_kernel<<<(total + 255) / 256, 256>>>(out);
}

// round 2
// speedup vs baseline: 1.1169x; 1.1169x over previous
#include <cuda_runtime.h>

// Problem constants (fixed by setup_inputs)
#define BATCH   16
#define CHAN    4
#define H_IN    128
#define W_IN    240
#define MAXD    24
#define H_OUT   1024
#define W_OUT   1920
#define W4      (W_OUT / 4)   // 480

// ---------------------------------------------------------------------------
// Fused kernel: one block per (b, y_in).
//  Phase 1: load feat_l/feat_r rows y and y+1 (4 channels) into smem.
//  Phase 2: compute pred rows y, y+1 (cost volume + softmax expectation) -> smem.
//  Phase 3: emit all output rows oy with floor(oy*ysc)==y via smem bilinear.
// ---------------------------------------------------------------------------
__global__ __launch_bounds__(256) void fused_kernel(
    const float* __restrict__ fl, const float* __restrict__ fr,
    float* __restrict__ out)
{
    const int blk = blockIdx.x;        // b*H_IN + y
    const int b = blk >> 7;            // /128
    const int y = blk & (H_IN - 1);
    const int yb = min(y + 1, H_IN - 1);

    __shared__ float sl[2][CHAN][W_IN];
    __shared__ float sr[2][CHAN][W_IN];
    __shared__ float prow[2][W_IN + 1];   // +1 pad for x0=239 reads

    // ---- Phase 1: stage the 2x(l,r)x4-channel rows ----
    for (int i = threadIdx.x; i < 2 * CHAN * W_IN; i += 256) {
        const int x = i % W_IN;
        const int t = i / W_IN;
        const int c = t & 3;
        const int r = t >> 2;
        const int yy = r ? yb : y;
        const size_t off = (((size_t)b * CHAN + c) * H_IN + yy) * W_IN + x;
        sl[r][c][x] = fl[off];
        sr[r][c][x] = fr[off];
    }
    __syncthreads();

    // ---- Phase 2: disparity prediction for both rows ----
    const int x = threadIdx.x;
    if (x < W_IN) {
#pragma unroll
        for (int r = 0; r < 2; r++) {
            const float l0 = sl[r][0][x], l1 = sl[r][1][x];
            const float l2 = sl[r][2][x], l3 = sl[r][3][x];

            float cost[MAXD];
            float cmin = 3.402823e38f;
#pragma unroll
            for (int d = 0; d < MAXD; d++) {
                const int xs = x - d;
                float r0, r1, r2, r3;
                if (xs >= 0) {
                    r0 = sr[r][0][xs]; r1 = sr[r][1][xs];
                    r2 = sr[r][2][xs]; r3 = sr[r][3][xs];
                } else {
                    r0 = r1 = r2 = r3 = 0.0f;   // zero padding
                }
                const float c = fabsf(l0 - r0) + fabsf(l1 - r1)
                              + fabsf(l2 - r2) + fabsf(l3 - r3);
                cost[d] = c;
                cmin = fminf(cmin, c);
            }

            float num = 0.0f, den = 0.0f;
#pragma unroll
            for (int d = 0; d < MAXD; d++) {
                const float e = __expf(cmin - cost[d]);   // softmax(-cost)
                den += e;
                num += (float)d * e;
            }
            prow[r][x] = (num / den) * 8.0f;   // * (1024/128)
        }
    }
    __syncthreads();
    if (threadIdx.x < 2) prow[threadIdx.x][W_IN] = prow[threadIdx.x][W_IN - 1];
    __syncthreads();

    // ---- Phase 3: bilinear upsample, rows owned by this block ----
    // oy range with floor(oy * 127/1023) == y (exact integer partition)
    int oy_start = (y * (H_OUT - 1) + (H_IN - 2)) / (H_IN - 1);          // ceil(y*1023/127)
    int oy_end   = ((y + 1) * (H_OUT - 1) + (H_IN - 2)) / (H_IN - 1) - 1;
    if (oy_end > H_OUT - 1) oy_end = H_OUT - 1;

    const float ysc = (float)(H_IN - 1) / (float)(H_OUT - 1);
    const float xsc = (float)(W_IN - 1) / (float)(W_OUT - 1);

    const int nrow = oy_end - oy_start + 1;
    const int total4 = nrow * W4;
    float4* __restrict__ out4 = (float4*)out;

    for (int i = threadIdx.x; i < total4; i += 256) {
        const int r   = i / W4;
        const int ox4 = i - r * W4;
        const int oy  = oy_start + r;
        const float wy = (float)oy * ysc - (float)y;

        float4 res;
        float* rp = (float*)&res;
#pragma unroll
        for (int k = 0; k < 4; k++) {
            const int ox = ox4 * 4 + k;
            const float xf = (float)ox * xsc;
            const int x0 = (int)xf;          // xf >= 0, <= ~239.00002
            const float wx = xf - (float)x0;

            const float a0 = prow[0][x0], a1 = prow[0][x0 + 1];
            const float b0 = prow[1][x0], b1 = prow[1][x0 + 1];
            const float v0 = a0 + wx * (a1 - a0);   // x-lerp, row y
            const float v1 = b0 + wx * (b1 - b0);   // x-lerp, row y+1
            rp[k] = v0 + wy * (v1 - v0);            // y-lerp
        }
        out4[((size_t)b * H_OUT + oy) * W4 + ox4] = res;
    }
}

extern "C" void kernel_launch(void* const* d_in, const int* in_sizes, int n_in,
                              void* d_out, int out_size)
{
    const float* feat_l = (const float*)d_in[0];
    const float* feat_r = (const float*)d_in[1];
    float* out = (float*)d_out;

    fused_kernel<<<BATCH * H_IN, 256>>>(feat_l, feat_r, out);
}

// round 3
// speedup vs baseline: 1.4287x; 1.2791x over previous
#include <cuda_runtime.h>

// Problem constants (fixed by setup_inputs)
#define BATCH   16
#define CHAN    4
#define H_IN    128
#define W_IN    240
#define MAXD    24
#define H_OUT   1024
#define W_OUT   1920
#define W4      (W_OUT / 4)     // 480
#define TILE    8               // input rows per block
#define NTILES  (H_IN / TILE)   // 16
#define NTHREADS 512
#define NWARPS  (NTHREADS / 32)

// ---------------------------------------------------------------------------
// Fully fused, tiled kernel. One block per (batch, 8-input-row tile).
//  Phase A: compute 9 pred rows (8 + halo) into smem, channels packed float4.
//  Phase B: warp-per-output-row separable bilinear upsample from smem.
// ---------------------------------------------------------------------------
__global__ __launch_bounds__(NTHREADS, 2) void fused_kernel(
    const float* __restrict__ fl, const float* __restrict__ fr,
    float* __restrict__ out)
{
    const int blk = blockIdx.x;          // b*NTILES + ty
    const int b  = blk >> 4;
    const int ty = blk & (NTILES - 1);
    const int base_y = ty * TILE;

    __shared__ float4 sl4[2][W_IN];          // 2 staged rows, channel-packed
    __shared__ float4 sr4[2][W_IN];
    __shared__ float  prow[TILE + 1][W_IN + 1];
    __shared__ float  vrow_s[NWARPS][W_IN + 1];

    const int half = threadIdx.x >> 8;       // 0 or 1 (row within pair)
    const int t256 = threadIdx.x & 255;

    // ---- Phase A: disparity prediction for 9 rows, two at a time ----
    for (int rr = 0; rr < TILE + 1; rr += 2) {
        const int nr = min(2, TILE + 1 - rr);

        // stage: each 256-thread half loads one row (l+r, 4 channels)
        if (half < nr) {
            const int yy = min(base_y + rr + half, H_IN - 1);
            const size_t rbase = ((size_t)b * CHAN) * (H_IN * W_IN)
                               + (size_t)yy * W_IN;
            for (int i = t256; i < 2 * CHAN * W_IN; i += 256) {  // 1920 items
                const int x   = i % W_IN;
                const int tt  = i / W_IN;          // 0..7
                const int c   = tt & 3;
                const int img = tt >> 2;
                const size_t off = rbase + (size_t)c * (H_IN * W_IN) + x;
                const float v = img ? fr[off] : fl[off];
                float* dst = img ? (float*)&sr4[half][x] : (float*)&sl4[half][x];
                dst[c] = v;
            }
        }
        __syncthreads();

        // compute: threads t256<240 of each active half do one pixel
        if (half < nr && t256 < W_IN) {
            const int x = t256;
            const float4 L = sl4[half][x];
            const float absl = fabsf(L.x) + fabsf(L.y) + fabsf(L.z) + fabsf(L.w);

            float num = 0.0f, den = 0.0f;
#pragma unroll
            for (int d = 0; d < MAXD; d++) {
                const int xs = x - d;
                float c;
                if (xs >= 0) {
                    const float4 R = sr4[half][xs];
                    c = fabsf(L.x - R.x) + fabsf(L.y - R.y)
                      + fabsf(L.z - R.z) + fabsf(L.w - R.w);
                } else {
                    c = absl;                     // zero padding
                }
                const float e = __expf(-c);       // softmax(-cost), unshifted
                den += e;
                num += (float)d * e;
            }
            prow[rr + half][x] = (num / den) * 8.0f;   // * (1024/128)
        }
        __syncthreads();
    }
    if (threadIdx.x < TILE + 1)
        prow[threadIdx.x][W_IN] = prow[threadIdx.x][W_IN - 1];  // x-pad
    __syncthreads();

    // ---- Phase B: separable bilinear upsample, warp-per-output-row ----
    // rows owned: floor(oy*127/1023) in [base_y, base_y+7]
    const int oy_start = (base_y * (H_OUT - 1) + (H_IN - 2)) / (H_IN - 1);
    const int oy_end   = min(H_OUT - 1,
        ((base_y + TILE) * (H_OUT - 1) + (H_IN - 2)) / (H_IN - 1) - 1);

    const float ysc = (float)(H_IN - 1) / (float)(H_OUT - 1);
    const float xsc = (float)(W_IN - 1) / (float)(W_OUT - 1);

    const int warp = threadIdx.x >> 5;
    const int lane = threadIdx.x & 31;
    float* __restrict__ vrow = vrow_s[warp];

    for (int oy = oy_start + warp; oy <= oy_end; oy += NWARPS) {
        const int y0 = (oy * (H_IN - 1)) / (H_OUT - 1);   // exact
        const int r  = y0 - base_y;                        // 0..7
        const float wy = (float)oy * ysc - (float)y0;

        const float* __restrict__ p0 = prow[r];
        const float* __restrict__ p1 = prow[r + 1];
        for (int x = lane; x < W_IN + 1; x += 32) {
            const float a = p0[x];
            vrow[x] = a + wy * (p1[x] - a);
        }
        __syncwarp();

        float4* __restrict__ orow =
            (float4*)(out + ((size_t)b * H_OUT + oy) * W_OUT);
        for (int i4 = lane; i4 < W4; i4 += 32) {
            const float xf0 = (float)(i4 * 4) * xsc;
            float4 res;
            float* rp = (float*)&res;
#pragma unroll
            for (int k = 0; k < 4; k++) {
                const float xk = xf0 + (float)k * xsc;
                const int x0 = (int)xk;
                const float wx = xk - (float)x0;
                const float v0 = vrow[x0];
                const float v1 = vrow[x0 + 1];
                rp[k] = v0 + wx * (v1 - v0);
            }
            orow[i4] = res;
        }
        __syncwarp();
    }
}

extern "C" void kernel_launch(void* const* d_in, const int* in_sizes, int n_in,
                              void* d_out, int out_size)
{
    const float* feat_l = (const float*)d_in[0];
    const float* feat_r = (const float*)d_in[1];
    float* out = (float*)d_out;

    fused_kernel<<<BATCH * NTILES, NTHREADS>>>(feat_l, feat_r, out);
}